// round 7
// baseline (speedup 1.0000x reference)
#include <cuda_runtime.h>
#include <cuda_bf16.h>
#include <math.h>

#define BB 4
#define TT 1024
#define DD 256
#define VV 32000
#define NROWS (BB*TT)            // 4096
#define LOGITS_N ((long long)NROWS * VV)   // 131,072,000

typedef unsigned long long u64;

// ---------------- device scratch (no allocations allowed) ----------------
__device__ float g_xp0[NROWS * DD];   // layer0 input projection, row = t*4+b
__device__ float g_rnn[NROWS * DD];   // h1[t] outputs, row = b*1024+t (matches out rows)
__device__ float g_final[2 * BB * DD];

// ---------------- f32x2 helpers ----------------
__device__ __forceinline__ u64 ffma2(u64 a, u64 b, u64 c) {
    u64 d; asm("fma.rn.f32x2 %0, %1, %2, %3;" : "=l"(d) : "l"(a), "l"(b), "l"(c)); return d;
}
__device__ __forceinline__ u64 dup2(float a) {
    u64 d; asm("mov.b64 %0, {%1, %1};" : "=l"(d) : "f"(a)); return d;
}
__device__ __forceinline__ float red2(u64 a) {
    float lo, hi; asm("mov.b64 {%0, %1}, %2;" : "=f"(lo), "=f"(hi) : "l"(a)); return lo + hi;
}
__device__ __forceinline__ float2 up2(u64 a) {
    float2 r; asm("mov.b64 {%0, %1}, %2;" : "=f"(r.x), "=f"(r.y) : "l"(a)); return r;
}
__device__ __forceinline__ unsigned int smem_u32(const void* p) {
    return (unsigned int)__cvta_generic_to_shared(p);
}
__device__ __forceinline__ void cluster_sync_all() {
    asm volatile("barrier.cluster.arrive.aligned;" ::: "memory");
    asm volatile("barrier.cluster.wait.aligned;"   ::: "memory");
}
// store one float to the same smem offset in all 8 cluster CTAs
__device__ __forceinline__ void bcast_store8(unsigned int laddr, float v) {
#pragma unroll
    for (int rk = 0; rk < 8; ++rk) {
        unsigned int ra;
        asm volatile("mapa.shared::cluster.u32 %0, %1, %2;" : "=r"(ra) : "r"(laddr), "r"(rk));
        asm volatile("st.shared::cluster.f32 [%0], %1;" :: "r"(ra), "f"(v) : "memory");
    }
}

// ===========================================================================
// Kernel 1: embedding gather + x-projection of layer 0.
// g_xp0[(t*4+b)*256 + d] = b0[d] + sum_k embed[ids[b,t],k] * W0[d,k]
// grid 512 blocks x 256 threads; 8 rows per block.
// ===========================================================================
__global__ __launch_bounds__(256) void xproj_kernel(
    const int*   __restrict__ ids,
    const float* __restrict__ embed,
    const float* __restrict__ W0,
    const float* __restrict__ b0)
{
    __shared__ __align__(16) float xs_t[DD * 8];   // [k][j] transposed x rows
    __shared__ int sid[8];

    const int tid = threadIdx.x;
    const int r0  = blockIdx.x * 8;

    if (tid < 8) {
        int r = r0 + tid;            // row = t*4 + b
        int t = r >> 2, b = r & 3;
        sid[tid] = ids[b * TT + t];
    }
    __syncthreads();

    // gather 8 embedding rows, transposed: xs_t[k*8 + j]
    for (int idx = tid; idx < DD * 8; idx += 256) {
        int j = idx & 7;
        int k = idx >> 3;
        xs_t[idx] = embed[(long long)sid[j] * DD + k];
    }
    __syncthreads();

    const int d = tid;               // one output feature per thread
    const float4* wrow = (const float4*)(W0 + (long long)d * (2 * DD)); // x-part cols 0..255

    u64 acc[4];                      // j-pairs {0,1},{2,3},{4,5},{6,7}
#pragma unroll
    for (int p = 0; p < 4; ++p) acc[p] = 0ULL;

#pragma unroll 8
    for (int kq = 0; kq < DD / 4; ++kq) {
        float4 w4 = wrow[kq];
        const ulonglong2* xp = (const ulonglong2*)(xs_t + (kq * 4) * 8);
        float wk[4] = {w4.x, w4.y, w4.z, w4.w};
#pragma unroll
        for (int c = 0; c < 4; ++c) {
            ulonglong2 x01 = xp[2 * c + 0];     // j pairs (0,1),(2,3)
            ulonglong2 x23 = xp[2 * c + 1];     // j pairs (4,5),(6,7)
            u64 wd = dup2(wk[c]);
            acc[0] = ffma2(wd, x01.x, acc[0]);
            acc[1] = ffma2(wd, x01.y, acc[1]);
            acc[2] = ffma2(wd, x23.x, acc[2]);
            acc[3] = ffma2(wd, x23.y, acc[3]);
        }
    }
    float bd = b0[d];
#pragma unroll
    for (int p = 0; p < 4; ++p) {
        float2 v = up2(acc[p]);
        g_xp0[(long long)(r0 + 2 * p + 0) * DD + d] = bd + v.x;
        g_xp0[(long long)(r0 + 2 * p + 1) * DD + d] = bd + v.y;
    }
}

// ===========================================================================
// Kernel 2: the recurrence. 8-CTA cluster, CTA r owns d in [r*32, r*32+32).
// ===========================================================================
#define SW0 260                     // padded row width (k=256), stride%32=4 -> conflict free
#define SW1 516                     // padded row width (j=512)
#define HROW 260
#define HBUF (BB * HROW)            // 1040 floats per parity buffer
// smem float offsets
#define OFF_W0H 0
#define OFF_W1  (32 * SW0)                    // 8320
#define OFF_H0  (OFF_W1 + 32 * SW1)           // 24832
#define OFF_H1  (OFF_H0 + 2 * HBUF)           // 26912
#define RNN_SMEM_FLOATS (OFF_H1 + 2 * HBUF)   // 28992
#define RNN_SMEM_BYTES  (RNN_SMEM_FLOATS * 4) // 115968

__global__ __launch_bounds__(256, 1) __cluster_dims__(8, 1, 1)
void rnn_kernel(const float* __restrict__ W0,
                const float* __restrict__ W1,
                const float* __restrict__ b1)
{
    extern __shared__ __align__(16) float sm[];
    float* W0h_s = sm + OFF_W0H;
    float* W1_s  = sm + OFF_W1;
    float* h0b   = sm + OFF_H0;
    float* h1b   = sm + OFF_H1;

    const int tid  = threadIdx.x;
    const int r    = blockIdx.x;          // cluster rank == blockIdx.x for 1-D cluster
    const int base = r * 32;

    // load weight slices (coalesced over k)
    for (int idx = tid; idx < 32 * 256; idx += 256) {
        int dl = idx >> 8, k = idx & 255;
        W0h_s[dl * SW0 + k] = W0[(long long)(base + dl) * 512 + 256 + k];
    }
    for (int idx = tid; idx < 32 * 512; idx += 256) {
        int dl = idx >> 9, j = idx & 511;
        W1_s[dl * SW1 + j] = W1[(long long)(base + dl) * 512 + j];
    }
    // zero ONLY parity-0 h buffers (parity-1 gets remote-written at t=0)
    for (int idx = tid; idx < HBUF; idx += 256) {
        h0b[idx] = 0.0f;
        h1b[idx] = 0.0f;
    }

    const int w  = tid >> 5;
    const int l  = tid & 31;
    const int dl = ((w & 3) << 3) | (l & 7);
    const int b  = l >> 3;
    const int dg = base + dl;
    const float b1v = b1[dg];

    cluster_sync_all();   // weights + zeroed buffers visible everywhere before step 0

    for (int t = 0; t < TT; ++t) {
        const int pr = t & 1;
        const int pw = pr ^ 1;

        if (w < 4) {
            // ----- layer 0: h0 = tanh(xp0[t] + W0h . h0_prev) -----
            float xp = g_xp0[(long long)(t * 4 + b) * DD + dg];
            const ulonglong2* wr = (const ulonglong2*)(W0h_s + dl * SW0);
            const ulonglong2* hr = (const ulonglong2*)(h0b + pr * HBUF + b * HROW);
            u64 a0 = 0, a1 = 0, a2 = 0, a3 = 0;
#pragma unroll 16
            for (int q = 0; q < 64; q += 2) {        // 64 ulonglong2 = 256 floats
                ulonglong2 wv0 = wr[q],     wv1 = wr[q + 1];
                ulonglong2 hv0 = hr[q],     hv1 = hr[q + 1];
                a0 = ffma2(wv0.x, hv0.x, a0);
                a1 = ffma2(wv0.y, hv0.y, a1);
                a2 = ffma2(wv1.x, hv1.x, a2);
                a3 = ffma2(wv1.y, hv1.y, a3);
            }
            float s = (red2(a0) + red2(a1)) + (red2(a2) + red2(a3));
            float h0v = tanhf(xp + s);
            bcast_store8(smem_u32(&h0b[pw * HBUF + b * HROW + dg]), h0v);
            if (t == TT - 1) g_final[0 * BB * DD + b * DD + dg] = h0v;
        }
        cluster_sync_all();   // h0[t] visible in every CTA

        if (w >= 4) {
            // ----- layer 1: h1 = tanh(b1 + W1[:, :256] . h0[t] + W1[:, 256:] . h1_prev) -----
            const ulonglong2* wr  = (const ulonglong2*)(W1_s + dl * SW1);
            const ulonglong2* h0r = (const ulonglong2*)(h0b + pw * HBUF + b * HROW);
            const ulonglong2* h1r = (const ulonglong2*)(h1b + pr * HBUF + b * HROW);
            u64 a0 = 0, a1 = 0, a2 = 0, a3 = 0;
#pragma unroll 16
            for (int q = 0; q < 64; q += 2) {        // cols 0..255 . h0[t]
                ulonglong2 wv0 = wr[q],     wv1 = wr[q + 1];
                ulonglong2 hv0 = h0r[q],    hv1 = h0r[q + 1];
                a0 = ffma2(wv0.x, hv0.x, a0);
                a1 = ffma2(wv0.y, hv0.y, a1);
                a2 = ffma2(wv1.x, hv1.x, a2);
                a3 = ffma2(wv1.y, hv1.y, a3);
            }
#pragma unroll 16
            for (int q = 0; q < 64; q += 2) {        // cols 256..511 . h1[t-1]
                ulonglong2 wv0 = wr[64 + q], wv1 = wr[64 + q + 1];
                ulonglong2 hv0 = h1r[q],     hv1 = h1r[q + 1];
                a0 = ffma2(wv0.x, hv0.x, a0);
                a1 = ffma2(wv0.y, hv0.y, a1);
                a2 = ffma2(wv1.x, hv1.x, a2);
                a3 = ffma2(wv1.y, hv1.y, a3);
            }
            float s = (red2(a0) + red2(a1)) + (red2(a2) + red2(a3));
            float h1v = tanhf(b1v + s);
            bcast_store8(smem_u32(&h1b[pw * HBUF + b * HROW + dg]), h1v);
            g_rnn[(long long)(b * TT + t) * DD + dg] = h1v;
            if (t == TT - 1) g_final[1 * BB * DD + b * DD + dg] = h1v;
        }
        cluster_sync_all();   // h1[t] visible; WAR-safe for next step
    }
}

// ===========================================================================
// Kernel 3: head GEMM. logits[r, v] = g_rnn[r, :] . head_w[v, :]
// 128x128 tile, K-chunks of 32, 8m x 8v per thread, all f32x2.
// ===========================================================================
#define BM 128
#define BV 128
#define BK 32
#define TP 132                      // padded tile row (k-major)

__global__ __launch_bounds__(256) void head_kernel(
    const float* __restrict__ head_w,
    float* __restrict__ out)
{
    __shared__ __align__(16) float As[BK * TP];   // As[k][m]
    __shared__ __align__(16) float Bs[BK * TP];   // Bs[k][v]

    const int tid   = threadIdx.x;
    const int vTile = blockIdx.x;    // 0..249
    const int mTile = blockIdx.y;    // 0..31

    const int tv = tid & 15;         // 16
    const int tm = tid >> 4;         // 16
    const int lkq = tid & 7;         // load mapping: k-quad
    const int lr0 = tid >> 3;        // load mapping: row 0..31 (+32*i)

    u64 acc[8][4];
#pragma unroll
    for (int mi = 0; mi < 8; ++mi)
#pragma unroll
        for (int vp = 0; vp < 4; ++vp) acc[mi][vp] = 0ULL;

    const long long mBase = (long long)mTile * BM;
    const long long vBase = (long long)vTile * BV;

    for (int kc = 0; kc < DD; kc += BK) {
        // ---- load A tile (g_rnn rows) and B tile (head_w rows), k-major in smem ----
#pragma unroll
        for (int i = 0; i < 4; ++i) {
            int m = lr0 + 32 * i;
            float4 av = *(const float4*)(g_rnn + (mBase + m) * DD + kc + lkq * 4);
            As[(lkq * 4 + 0) * TP + m] = av.x;
            As[(lkq * 4 + 1) * TP + m] = av.y;
            As[(lkq * 4 + 2) * TP + m] = av.z;
            As[(lkq * 4 + 3) * TP + m] = av.w;

            int v = lr0 + 32 * i;
            float4 bv = *(const float4*)(head_w + (vBase + v) * DD + kc + lkq * 4);
            Bs[(lkq * 4 + 0) * TP + v] = bv.x;
            Bs[(lkq * 4 + 1) * TP + v] = bv.y;
            Bs[(lkq * 4 + 2) * TP + v] = bv.z;
            Bs[(lkq * 4 + 3) * TP + v] = bv.w;
        }
        __syncthreads();

        // ---- compute ----
#pragma unroll 8
        for (int k = 0; k < BK; ++k) {
            const float4* ap = (const float4*)(As + k * TP + tm * 8);
            float4 a0 = ap[0], a1 = ap[1];
            const ulonglong2* bp = (const ulonglong2*)(Bs + k * TP + tv * 8);
            ulonglong2 bq0 = bp[0], bq1 = bp[1];
            u64 bv0 = bq0.x, bv1 = bq0.y, bv2 = bq1.x, bv3 = bq1.y;
            float am[8] = {a0.x, a0.y, a0.z, a0.w, a1.x, a1.y, a1.z, a1.w};
#pragma unroll
            for (int mi = 0; mi < 8; ++mi) {
                u64 ad = dup2(am[mi]);
                acc[mi][0] = ffma2(ad, bv0, acc[mi][0]);
                acc[mi][1] = ffma2(ad, bv1, acc[mi][1]);
                acc[mi][2] = ffma2(ad, bv2, acc[mi][2]);
                acc[mi][3] = ffma2(ad, bv3, acc[mi][3]);
            }
        }
        __syncthreads();
    }

    // ---- epilogue ----
    const long long vOut = vBase + tv * 8;
#pragma unroll
    for (int mi = 0; mi < 8; ++mi) {
        long long row = mBase + tm * 8 + mi;
        float2 p0 = up2(acc[mi][0]);
        float2 p1 = up2(acc[mi][1]);
        float2 p2 = up2(acc[mi][2]);
        float2 p3 = up2(acc[mi][3]);
        float4 o0 = make_float4(p0.x, p0.y, p1.x, p1.y);
        float4 o1 = make_float4(p2.x, p2.y, p3.x, p3.y);
        float* dst = out + row * VV + vOut;
        *(float4*)(dst + 0) = o0;
        *(float4*)(dst + 4) = o1;
    }
}

// ===========================================================================
// Kernel 4: append final_hidden (2, B, D) after logits if the output has room.
// ===========================================================================
__global__ void tail_kernel(float* __restrict__ out, int n)
{
    int i = blockIdx.x * blockDim.x + threadIdx.x;
    if (i < n) out[LOGITS_N + i] = g_final[i];
}

// ===========================================================================
extern "C" void kernel_launch(void* const* d_in, const int* in_sizes, int n_in,
                              void* d_out, int out_size)
{
    const int*   ids    = (const int*)  d_in[0];
    const float* embed  = (const float*)d_in[1];
    const float* W0     = (const float*)d_in[2];
    const float* b0     = (const float*)d_in[3];
    const float* W1     = (const float*)d_in[4];
    const float* b1     = (const float*)d_in[5];
    const float* head_w = (const float*)d_in[6];
    float* out = (float*)d_out;

    cudaFuncSetAttribute(rnn_kernel, cudaFuncAttributeMaxDynamicSharedMemorySize,
                         RNN_SMEM_BYTES);

    xproj_kernel<<<NROWS / 8, 256>>>(ids, embed, W0, b0);
    rnn_kernel<<<8, 256, RNN_SMEM_BYTES>>>(W0, W1, b1);
    head_kernel<<<dim3(VV / BV, NROWS / BM), 256>>>(head_w, out);

    long long extra = (long long)out_size - LOGITS_N;
    if (extra > 0) {
        int n = (int)(extra < 2LL * BB * DD ? extra : 2LL * BB * DD);
        tail_kernel<<<(n + 255) / 256, 256>>>(out, n);
    }
}

// round 8
// speedup vs baseline: 1.1363x; 1.1363x over previous
#include <cuda_runtime.h>
#include <cuda_bf16.h>
#include <math.h>

#define BB 4
#define TT 1024
#define DD 256
#define VV 32000
#define NROWS (BB*TT)            // 4096
#define LOGITS_N ((long long)NROWS * VV)   // 131,072,000

typedef unsigned long long u64;

// ---------------- device scratch (no allocations allowed) ----------------
__device__ float g_xp0[NROWS * DD];   // layer0 input projection, row = t*4+b
__device__ float g_rnn[NROWS * DD];   // h1[t] outputs, row = b*1024+t (matches out rows)
__device__ float g_final[2 * BB * DD];

// ---------------- f32x2 helpers ----------------
__device__ __forceinline__ u64 ffma2(u64 a, u64 b, u64 c) {
    u64 d; asm("fma.rn.f32x2 %0, %1, %2, %3;" : "=l"(d) : "l"(a), "l"(b), "l"(c)); return d;
}
__device__ __forceinline__ u64 dup2(float a) {
    u64 d; asm("mov.b64 %0, {%1, %1};" : "=l"(d) : "f"(a)); return d;
}
__device__ __forceinline__ float red2(u64 a) {
    float lo, hi; asm("mov.b64 {%0, %1}, %2;" : "=f"(lo), "=f"(hi) : "l"(a)); return lo + hi;
}
__device__ __forceinline__ float2 up2(u64 a) {
    float2 r; asm("mov.b64 {%0, %1}, %2;" : "=f"(r.x), "=f"(r.y) : "l"(a)); return r;
}
__device__ __forceinline__ unsigned int smem_u32(const void* p) {
    return (unsigned int)__cvta_generic_to_shared(p);
}
__device__ __forceinline__ void cluster_sync_all() {
    asm volatile("barrier.cluster.arrive.aligned;" ::: "memory");
    asm volatile("barrier.cluster.wait.aligned;"   ::: "memory");
}
// store one float to the same smem offset in all 8 cluster CTAs
__device__ __forceinline__ void bcast_store8(unsigned int laddr, float v) {
#pragma unroll
    for (int rk = 0; rk < 8; ++rk) {
        unsigned int ra;
        asm volatile("mapa.shared::cluster.u32 %0, %1, %2;" : "=r"(ra) : "r"(laddr), "r"(rk));
        asm volatile("st.shared::cluster.f32 [%0], %1;" :: "r"(ra), "f"(v) : "memory");
    }
}

// ===========================================================================
// Kernel 1: embedding gather + x-projection of layer 0.
// g_xp0[(t*4+b)*256 + d] = b0[d] + sum_k embed[ids[b,t],k] * W0[d,k]
// grid 512 blocks x 256 threads; 8 rows per block.
// ===========================================================================
__global__ __launch_bounds__(256) void xproj_kernel(
    const int*   __restrict__ ids,
    const float* __restrict__ embed,
    const float* __restrict__ W0,
    const float* __restrict__ b0)
{
    __shared__ __align__(16) float xs_t[DD * 8];   // [k][j] transposed x rows
    __shared__ int sid[8];

    const int tid = threadIdx.x;
    const int r0  = blockIdx.x * 8;

    if (tid < 8) {
        int r = r0 + tid;            // row = t*4 + b
        int t = r >> 2, b = r & 3;
        sid[tid] = ids[b * TT + t];
    }
    __syncthreads();

    // gather 8 embedding rows, transposed: xs_t[k*8 + j]
    for (int idx = tid; idx < DD * 8; idx += 256) {
        int j = idx & 7;
        int k = idx >> 3;
        xs_t[idx] = embed[(long long)sid[j] * DD + k];
    }
    __syncthreads();

    const int d = tid;               // one output feature per thread
    const float4* wrow = (const float4*)(W0 + (long long)d * (2 * DD)); // x-part cols 0..255

    u64 acc[4];                      // j-pairs {0,1},{2,3},{4,5},{6,7}
#pragma unroll
    for (int p = 0; p < 4; ++p) acc[p] = 0ULL;

#pragma unroll 8
    for (int kq = 0; kq < DD / 4; ++kq) {
        float4 w4 = wrow[kq];
        const ulonglong2* xp = (const ulonglong2*)(xs_t + (kq * 4) * 8);
        float wk[4] = {w4.x, w4.y, w4.z, w4.w};
#pragma unroll
        for (int c = 0; c < 4; ++c) {
            ulonglong2 x01 = xp[2 * c + 0];     // j pairs (0,1),(2,3)
            ulonglong2 x23 = xp[2 * c + 1];     // j pairs (4,5),(6,7)
            u64 wd = dup2(wk[c]);
            acc[0] = ffma2(wd, x01.x, acc[0]);
            acc[1] = ffma2(wd, x01.y, acc[1]);
            acc[2] = ffma2(wd, x23.x, acc[2]);
            acc[3] = ffma2(wd, x23.y, acc[3]);
        }
    }
    float bd = b0[d];
#pragma unroll
    for (int p = 0; p < 4; ++p) {
        float2 v = up2(acc[p]);
        g_xp0[(long long)(r0 + 2 * p + 0) * DD + d] = bd + v.x;
        g_xp0[(long long)(r0 + 2 * p + 1) * DD + d] = bd + v.y;
    }
}

// ===========================================================================
// Kernel 2: the recurrence. 8-CTA cluster, CTA r owns d in [r*32, r*32+32).
// SKEWED pipeline: at tick i, warps 0-3 compute h0[i] while warps 4-7
// compute h1[i-1]. ONE cluster sync per tick.
//
// Buffer convention: h0[t] lives in h0b parity (t+1)&1; h1[t] in h1b parity
// (t+1)&1. At tick i:
//   layer0: reads h0[i-1] (buf i&1), writes h0[i] (buf (i+1)&1)
//   layer1: reads h0[i-1] (buf i&1), h1[i-2] (buf (i-1)&1), writes h1[i-1] (buf i&1)
// No same-tick read/write collision; WAR overwrites trail last reader by one sync.
// ===========================================================================
#define SW0 260                     // padded row width (k=256), stride%32=4 -> conflict free
#define SW1 516                     // padded row width (j=512)
#define HROW 260
#define HBUF (BB * HROW)            // 1040 floats per parity buffer
// smem float offsets
#define OFF_W0H 0
#define OFF_W1  (32 * SW0)                    // 8320
#define OFF_H0  (OFF_W1 + 32 * SW1)           // 24832
#define OFF_H1  (OFF_H0 + 2 * HBUF)           // 26912
#define RNN_SMEM_FLOATS (OFF_H1 + 2 * HBUF)   // 28992
#define RNN_SMEM_BYTES  (RNN_SMEM_FLOATS * 4) // 115968

__global__ __launch_bounds__(256, 1) __cluster_dims__(8, 1, 1)
void rnn_kernel(const float* __restrict__ W0,
                const float* __restrict__ W1,
                const float* __restrict__ b1)
{
    extern __shared__ __align__(16) float sm[];
    float* W0h_s = sm + OFF_W0H;
    float* W1_s  = sm + OFF_W1;
    float* h0b   = sm + OFF_H0;
    float* h1b   = sm + OFF_H1;

    const int tid  = threadIdx.x;
    const int r    = blockIdx.x;          // cluster rank == blockIdx.x for 1-D cluster
    const int base = r * 32;

    // load weight slices (coalesced over k)
    for (int idx = tid; idx < 32 * 256; idx += 256) {
        int dl = idx >> 8, k = idx & 255;
        W0h_s[dl * SW0 + k] = W0[(long long)(base + dl) * 512 + 256 + k];
    }
    for (int idx = tid; idx < 32 * 512; idx += 256) {
        int dl = idx >> 9, j = idx & 511;
        W1_s[dl * SW1 + j] = W1[(long long)(base + dl) * 512 + j];
    }
    // zero parity-0 buffers: h0[-1] (read at tick 0) and h1[-1] (read at tick 1)
    for (int idx = tid; idx < HBUF; idx += 256) {
        h0b[idx] = 0.0f;
        h1b[idx] = 0.0f;
    }

    const int w  = tid >> 5;
    const int l  = tid & 31;
    const int dl = ((w & 3) << 3) | (l & 7);
    const int b  = l >> 3;
    const int dg = base + dl;
    const float b1v = b1[dg];

    cluster_sync_all();   // weights + zeroed buffers visible everywhere before tick 0

    if (w < 4) {
        // ============== LAYER-0 WARPS: tick i computes h0[i] ==============
        float xp_cur = g_xp0[(long long)(0 * 4 + b) * DD + dg];
        const ulonglong2* wr = (const ulonglong2*)(W0h_s + dl * SW0);

        for (int i = 0; i <= TT; ++i) {
            if (i < TT) {
                // prefetch xp[i+1] — overlaps with the dot below
                float xp_nxt = 0.0f;
                if (i + 1 < TT)
                    xp_nxt = g_xp0[(long long)((i + 1) * 4 + b) * DD + dg];

                const int pr = i & 1;            // h0[i-1]
                const int pw = pr ^ 1;           // h0[i]
                const ulonglong2* hr = (const ulonglong2*)(h0b + pr * HBUF + b * HROW);
                u64 a0 = 0, a1 = 0, a2 = 0, a3 = 0;
#pragma unroll 16
                for (int q = 0; q < 64; q += 2) {        // 64 ulonglong2 = 256 floats
                    ulonglong2 wv0 = wr[q],     wv1 = wr[q + 1];
                    ulonglong2 hv0 = hr[q],     hv1 = hr[q + 1];
                    a0 = ffma2(wv0.x, hv0.x, a0);
                    a1 = ffma2(wv0.y, hv0.y, a1);
                    a2 = ffma2(wv1.x, hv1.x, a2);
                    a3 = ffma2(wv1.y, hv1.y, a3);
                }
                float s = (red2(a0) + red2(a1)) + (red2(a2) + red2(a3));
                float h0v = tanhf(xp_cur + s);
                bcast_store8(smem_u32(&h0b[pw * HBUF + b * HROW + dg]), h0v);
                if (i == TT - 1) g_final[0 * BB * DD + b * DD + dg] = h0v;
                xp_cur = xp_nxt;
            }
            cluster_sync_all();
        }
    } else {
        // ============== LAYER-1 WARPS: tick i computes h1[i-1] ==============
        const ulonglong2* wr = (const ulonglong2*)(W1_s + dl * SW1);

        for (int i = 0; i <= TT; ++i) {
            if (i > 0) {
                const int t    = i - 1;
                const int ph0  = i & 1;          // h0[i-1]
                const int ph1r = (i - 1) & 1;    // h1[i-2]
                const int ph1w = i & 1;          // h1[i-1]
                const ulonglong2* h0r = (const ulonglong2*)(h0b + ph0  * HBUF + b * HROW);
                const ulonglong2* h1r = (const ulonglong2*)(h1b + ph1r * HBUF + b * HROW);
                u64 a0 = 0, a1 = 0, a2 = 0, a3 = 0;
#pragma unroll 16
                for (int q = 0; q < 64; q += 2) {        // cols 0..255 . h0[t]
                    ulonglong2 wv0 = wr[q],     wv1 = wr[q + 1];
                    ulonglong2 hv0 = h0r[q],    hv1 = h0r[q + 1];
                    a0 = ffma2(wv0.x, hv0.x, a0);
                    a1 = ffma2(wv0.y, hv0.y, a1);
                    a2 = ffma2(wv1.x, hv1.x, a2);
                    a3 = ffma2(wv1.y, hv1.y, a3);
                }
#pragma unroll 16
                for (int q = 0; q < 64; q += 2) {        // cols 256..511 . h1[t-1]
                    ulonglong2 wv0 = wr[64 + q], wv1 = wr[64 + q + 1];
                    ulonglong2 hv0 = h1r[q],     hv1 = h1r[q + 1];
                    a0 = ffma2(wv0.x, hv0.x, a0);
                    a1 = ffma2(wv0.y, hv0.y, a1);
                    a2 = ffma2(wv1.x, hv1.x, a2);
                    a3 = ffma2(wv1.y, hv1.y, a3);
                }
                float s = (red2(a0) + red2(a1)) + (red2(a2) + red2(a3));
                float h1v = tanhf(b1v + s);
                bcast_store8(smem_u32(&h1b[ph1w * HBUF + b * HROW + dg]), h1v);
                g_rnn[(long long)(b * TT + t) * DD + dg] = h1v;
                if (t == TT - 1) g_final[1 * BB * DD + b * DD + dg] = h1v;
            }
            cluster_sync_all();
        }
    }
}

// ===========================================================================
// Kernel 3: head GEMM. logits[r, v] = g_rnn[r, :] . head_w[v, :]
// 128x128 tile, K-chunks of 32, 8m x 8v per thread, all f32x2.
// ===========================================================================
#define BM 128
#define BV 128
#define BK 32
#define TP 132                      // padded tile row (k-major)

__global__ __launch_bounds__(256) void head_kernel(
    const float* __restrict__ head_w,
    float* __restrict__ out)
{
    __shared__ __align__(16) float As[BK * TP];   // As[k][m]
    __shared__ __align__(16) float Bs[BK * TP];   // Bs[k][v]

    const int tid   = threadIdx.x;
    const int vTile = blockIdx.x;    // 0..249
    const int mTile = blockIdx.y;    // 0..31

    const int tv = tid & 15;         // 16
    const int tm = tid >> 4;         // 16
    const int lkq = tid & 7;         // load mapping: k-quad
    const int lr0 = tid >> 3;        // load mapping: row 0..31 (+32*i)

    u64 acc[8][4];
#pragma unroll
    for (int mi = 0; mi < 8; ++mi)
#pragma unroll
        for (int vp = 0; vp < 4; ++vp) acc[mi][vp] = 0ULL;

    const long long mBase = (long long)mTile * BM;
    const long long vBase = (long long)vTile * BV;

    for (int kc = 0; kc < DD; kc += BK) {
        // ---- load A tile (g_rnn rows) and B tile (head_w rows), k-major in smem ----
#pragma unroll
        for (int i = 0; i < 4; ++i) {
            int m = lr0 + 32 * i;
            float4 av = *(const float4*)(g_rnn + (mBase + m) * DD + kc + lkq * 4);
            As[(lkq * 4 + 0) * TP + m] = av.x;
            As[(lkq * 4 + 1) * TP + m] = av.y;
            As[(lkq * 4 + 2) * TP + m] = av.z;
            As[(lkq * 4 + 3) * TP + m] = av.w;

            int v = lr0 + 32 * i;
            float4 bv = *(const float4*)(head_w + (vBase + v) * DD + kc + lkq * 4);
            Bs[(lkq * 4 + 0) * TP + v] = bv.x;
            Bs[(lkq * 4 + 1) * TP + v] = bv.y;
            Bs[(lkq * 4 + 2) * TP + v] = bv.z;
            Bs[(lkq * 4 + 3) * TP + v] = bv.w;
        }
        __syncthreads();

        // ---- compute ----
#pragma unroll 8
        for (int k = 0; k < BK; ++k) {
            const float4* ap = (const float4*)(As + k * TP + tm * 8);
            float4 a0 = ap[0], a1 = ap[1];
            const ulonglong2* bp = (const ulonglong2*)(Bs + k * TP + tv * 8);
            ulonglong2 bq0 = bp[0], bq1 = bp[1];
            u64 bv0 = bq0.x, bv1 = bq0.y, bv2 = bq1.x, bv3 = bq1.y;
            float am[8] = {a0.x, a0.y, a0.z, a0.w, a1.x, a1.y, a1.z, a1.w};
#pragma unroll
            for (int mi = 0; mi < 8; ++mi) {
                u64 ad = dup2(am[mi]);
                acc[mi][0] = ffma2(ad, bv0, acc[mi][0]);
                acc[mi][1] = ffma2(ad, bv1, acc[mi][1]);
                acc[mi][2] = ffma2(ad, bv2, acc[mi][2]);
                acc[mi][3] = ffma2(ad, bv3, acc[mi][3]);
            }
        }
        __syncthreads();
    }

    // ---- epilogue ----
    const long long vOut = vBase + tv * 8;
#pragma unroll
    for (int mi = 0; mi < 8; ++mi) {
        long long row = mBase + tm * 8 + mi;
        float2 p0 = up2(acc[mi][0]);
        float2 p1 = up2(acc[mi][1]);
        float2 p2 = up2(acc[mi][2]);
        float2 p3 = up2(acc[mi][3]);
        float4 o0 = make_float4(p0.x, p0.y, p1.x, p1.y);
        float4 o1 = make_float4(p2.x, p2.y, p3.x, p3.y);
        float* dst = out + row * VV + vOut;
        *(float4*)(dst + 0) = o0;
        *(float4*)(dst + 4) = o1;
    }
}

// ===========================================================================
// Kernel 4: append final_hidden (2, B, D) after logits if the output has room.
// ===========================================================================
__global__ void tail_kernel(float* __restrict__ out, int n)
{
    int i = blockIdx.x * blockDim.x + threadIdx.x;
    if (i < n) out[LOGITS_N + i] = g_final[i];
}

// ===========================================================================
extern "C" void kernel_launch(void* const* d_in, const int* in_sizes, int n_in,
                              void* d_out, int out_size)
{
    const int*   ids    = (const int*)  d_in[0];
    const float* embed  = (const float*)d_in[1];
    const float* W0     = (const float*)d_in[2];
    const float* b0     = (const float*)d_in[3];
    const float* W1     = (const float*)d_in[4];
    const float* b1     = (const float*)d_in[5];
    const float* head_w = (const float*)d_in[6];
    float* out = (float*)d_out;

    cudaFuncSetAttribute(rnn_kernel, cudaFuncAttributeMaxDynamicSharedMemorySize,
                         RNN_SMEM_BYTES);

    xproj_kernel<<<NROWS / 8, 256>>>(ids, embed, W0, b0);
    rnn_kernel<<<8, 256, RNN_SMEM_BYTES>>>(W0, W1, b1);
    head_kernel<<<dim3(VV / BV, NROWS / BM), 256>>>(head_w, out);

    long long extra = (long long)out_size - LOGITS_N;
    if (extra > 0) {
        int n = (int)(extra < 2LL * BB * DD ? extra : 2LL * BB * DD);
        tail_kernel<<<(n + 255) / 256, 256>>>(out, n);
    }
}

// round 13
// speedup vs baseline: 1.5653x; 1.3775x over previous
#include <cuda_runtime.h>
#include <cuda_bf16.h>
#include <math.h>

#define BB 4
#define TT 1024
#define DD 256
#define VV 32000
#define NROWS (BB*TT)            // 4096
#define LOGITS_N ((long long)NROWS * VV)   // 131,072,000

typedef unsigned long long u64;

// ---------------- device scratch (no allocations allowed) ----------------
__device__ float g_xp0[NROWS * DD];   // layer0 input projection, row = t*4+b
__device__ float g_rnn[NROWS * DD];   // h1[t] outputs, row = b*1024+t
__device__ float g_final[2 * BB * DD];

// ---------------- f32x2 helpers ----------------
__device__ __forceinline__ u64 ffma2(u64 a, u64 b, u64 c) {
    u64 d; asm("fma.rn.f32x2 %0, %1, %2, %3;" : "=l"(d) : "l"(a), "l"(b), "l"(c)); return d;
}
__device__ __forceinline__ u64 dup2(float a) {
    u64 d; asm("mov.b64 %0, {%1, %1};" : "=l"(d) : "f"(a)); return d;
}
__device__ __forceinline__ float red2(u64 a) {
    float lo, hi; asm("mov.b64 {%0, %1}, %2;" : "=f"(lo), "=f"(hi) : "l"(a)); return lo + hi;
}
__device__ __forceinline__ float2 up2(u64 a) {
    float2 r; asm("mov.b64 {%0, %1}, %2;" : "=f"(r.x), "=f"(r.y) : "l"(a)); return r;
}
__device__ __forceinline__ unsigned int smem_u32(const void* p) {
    return (unsigned int)__cvta_generic_to_shared(p);
}
__device__ __forceinline__ void cluster_sync_all() {
    asm volatile("barrier.cluster.arrive.aligned;" ::: "memory");
    asm volatile("barrier.cluster.wait.aligned;"   ::: "memory");
}
__device__ __forceinline__ void st_cluster(unsigned int laddr, int rank, float v) {
    unsigned int ra;
    asm volatile("mapa.shared::cluster.u32 %0, %1, %2;" : "=r"(ra) : "r"(laddr), "r"(rank));
    asm volatile("st.shared::cluster.f32 [%0], %1;" :: "r"(ra), "f"(v) : "memory");
}

// ===========================================================================
// Kernel 1: embedding gather + x-projection of layer 0 (unchanged, known good)
// ===========================================================================
__global__ __launch_bounds__(256) void xproj_kernel(
    const int*   __restrict__ ids,
    const float* __restrict__ embed,
    const float* __restrict__ W0,
    const float* __restrict__ b0)
{
    __shared__ __align__(16) float xs_t[DD * 8];
    __shared__ int sid[8];

    const int tid = threadIdx.x;
    const int r0  = blockIdx.x * 8;

    if (tid < 8) {
        int r = r0 + tid;            // row = t*4 + b
        int t = r >> 2, b = r & 3;
        sid[tid] = ids[b * TT + t];
    }
    __syncthreads();

    for (int idx = tid; idx < DD * 8; idx += 256) {
        int j = idx & 7;
        int k = idx >> 3;
        xs_t[idx] = embed[(long long)sid[j] * DD + k];
    }
    __syncthreads();

    const int d = tid;
    const float4* wrow = (const float4*)(W0 + (long long)d * (2 * DD));

    u64 acc[4];
#pragma unroll
    for (int p = 0; p < 4; ++p) acc[p] = 0ULL;

#pragma unroll 8
    for (int kq = 0; kq < DD / 4; ++kq) {
        float4 w4 = wrow[kq];
        const ulonglong2* xp = (const ulonglong2*)(xs_t + (kq * 4) * 8);
        float wk[4] = {w4.x, w4.y, w4.z, w4.w};
#pragma unroll
        for (int c = 0; c < 4; ++c) {
            ulonglong2 x01 = xp[2 * c + 0];
            ulonglong2 x23 = xp[2 * c + 1];
            u64 wd = dup2(wk[c]);
            acc[0] = ffma2(wd, x01.x, acc[0]);
            acc[1] = ffma2(wd, x01.y, acc[1]);
            acc[2] = ffma2(wd, x23.x, acc[2]);
            acc[3] = ffma2(wd, x23.y, acc[3]);
        }
    }
    float bd = b0[d];
#pragma unroll
    for (int p = 0; p < 4; ++p) {
        float2 v = up2(acc[p]);
        g_xp0[(long long)(r0 + 2 * p + 0) * DD + d] = bd + v.x;
        g_xp0[(long long)(r0 + 2 * p + 1) * DD + d] = bd + v.y;
    }
}

// ===========================================================================
// Kernel 2: recurrence — weights in REGISTERS, h streamed from smem.
// 8-CTA cluster; CTA r owns d in [r*32, r*32+32). 384 threads:
//   warps 0-3  (128 thr): layer0, thread = (d_local 0..31, kc 0..3), 64 k each
//   warps 4-11 (256 thr): layer1, thread = (d_local 0..31, kc 0..7), 64 k each
// Each thread computes partials for all 4 batches; shfl.xor reduce over kc.
// Skewed pipeline: tick i computes h0[i] (L0 warps) and h1[i-1] (L1 warps);
// ONE cluster sync per tick.
// h buffers: h0[t] and h1[t] stored at parity (t+1)&1.
// ===========================================================================
#define HCH 68                       // padded 64-float chunk (bank stagger 4)
#define HB  (4 * HCH)                // 272: per-b row (4 chunks)
#define HPAR (BB * HB)               // 1088: per parity
#define OFF_H1F (2 * HPAR + 16)      // 2192: h1 region, +16 => banks offset by 16
#define RNN_SMEM_FLOATS (OFF_H1F + 2 * HPAR)   // 4368

__global__ __launch_bounds__(384, 1) __cluster_dims__(8, 1, 1)
void rnn_kernel(const float* __restrict__ W0,
                const float* __restrict__ W1,
                const float* __restrict__ b1)
{
    __shared__ __align__(16) float hbuf[RNN_SMEM_FLOATS];

    const int tid  = threadIdx.x;
    const int w    = tid >> 5;
    const int l    = tid & 31;
    const int r    = blockIdx.x;
    const int base = r * 32;

    for (int i = tid; i < RNN_SMEM_FLOATS; i += 384) hbuf[i] = 0.0f;

    if (w < 4) {
        // ================= LAYER-0 warps =================
        const int dl = w * 8 + (l & 7);
        const int kc = l >> 3;                 // 0..3, k range [kc*64, kc*64+64)
        const int dg = base + dl;
        const int hpos = (dg >> 6) * HCH + (dg & 63);

        u64 wreg[32];
        {
            const ulonglong2* ws = (const ulonglong2*)(W0 + (long long)dg * 512 + 256 + kc * 64);
#pragma unroll
            for (int j = 0; j < 16; ++j) { ulonglong2 v = ws[j]; wreg[2*j] = v.x; wreg[2*j+1] = v.y; }
        }
        float xp[4] = {0.f, 0.f, 0.f, 0.f};
        if (kc == 0) {
#pragma unroll
            for (int b = 0; b < 4; ++b) xp[b] = g_xp0[(long long)(0 * 4 + b) * DD + dg];
        }

        cluster_sync_all();   // zeros visible; ready for tick 0

        for (int i = 0; i <= TT; ++i) {
            if (i < TT) {
                const int pr = i & 1;          // h0[i-1]
                const int pw = pr ^ 1;         // h0[i]
                float xpn[4] = {0.f, 0.f, 0.f, 0.f};
                if (kc == 0 && i + 1 < TT) {
#pragma unroll
                    for (int b = 0; b < 4; ++b)
                        xpn[b] = g_xp0[(long long)((i + 1) * 4 + b) * DD + dg];
                }

                const float* hbase = hbuf + pr * HPAR + kc * HCH;
                u64 aX[4] = {0,0,0,0}, aY[4] = {0,0,0,0};
#pragma unroll
                for (int q = 0; q < 16; ++q) {
#pragma unroll
                    for (int b = 0; b < 4; ++b) {
                        ulonglong2 hv = ((const ulonglong2*)(hbase + b * HB))[q];
                        aX[b] = ffma2(wreg[2*q],   hv.x, aX[b]);
                        aY[b] = ffma2(wreg[2*q+1], hv.y, aY[b]);
                    }
                }
                float s[4];
#pragma unroll
                for (int b = 0; b < 4; ++b) {
                    s[b] = red2(aX[b]) + red2(aY[b]) + xp[b];  // xp nonzero only kc==0
                    s[b] += __shfl_xor_sync(0xffffffffu, s[b], 8);
                    s[b] += __shfl_xor_sync(0xffffffffu, s[b], 16);
                }
#pragma unroll
                for (int b = 0; b < 4; ++b) {
                    float h0v = tanhf(s[b]);
                    unsigned int la = smem_u32(&hbuf[pw * HPAR + b * HB + hpos]);
                    st_cluster(la, 2 * kc + 0, h0v);
                    st_cluster(la, 2 * kc + 1, h0v);
                    if (i == TT - 1 && kc == 0) g_final[b * DD + dg] = h0v;
                }
#pragma unroll
                for (int b = 0; b < 4; ++b) xp[b] = xpn[b];
            }
            cluster_sync_all();
        }
    } else {
        // ================= LAYER-1 warps =================
        const int w1 = w - 4;                  // 0..7
        const int dl = w1 * 4 + (l & 3);
        const int kc = l >> 2;                 // 0..7, k range [kc*64, kc*64+64) of 512
        const int dg = base + dl;
        const int hpos = (dg >> 6) * HCH + (dg & 63);

        u64 wreg[32];
        {
            // cols kc*64..kc*64+63: kc<4 pairs with h0[t], kc>=4 with h1[t-1]
            const ulonglong2* ws = (const ulonglong2*)(W1 + (long long)dg * 512 + kc * 64);
#pragma unroll
            for (int j = 0; j < 16; ++j) { ulonglong2 v = ws[j]; wreg[2*j] = v.x; wreg[2*j+1] = v.y; }
        }
        const float b1v = (kc == 0) ? b1[dg] : 0.0f;

        cluster_sync_all();

        for (int i = 0; i <= TT; ++i) {
            if (i > 0) {
                const int t    = i - 1;
                const int ph0  = i & 1;        // h0[i-1]
                const int ph1r = (i - 1) & 1;  // h1[i-2]
                const int ph1w = i & 1;        // h1[i-1]

                const float* hbase = (kc < 4)
                    ? hbuf + ph0 * HPAR + kc * HCH
                    : hbuf + OFF_H1F + ph1r * HPAR + (kc - 4) * HCH;

                u64 aX[4] = {0,0,0,0}, aY[4] = {0,0,0,0};
#pragma unroll
                for (int q = 0; q < 16; ++q) {
#pragma unroll
                    for (int b = 0; b < 4; ++b) {
                        ulonglong2 hv = ((const ulonglong2*)(hbase + b * HB))[q];
                        aX[b] = ffma2(wreg[2*q],   hv.x, aX[b]);
                        aY[b] = ffma2(wreg[2*q+1], hv.y, aY[b]);
                    }
                }
                float s[4];
#pragma unroll
                for (int b = 0; b < 4; ++b) {
                    s[b] = red2(aX[b]) + red2(aY[b]) + b1v;    // b1 nonzero only kc==0
                    s[b] += __shfl_xor_sync(0xffffffffu, s[b], 4);
                    s[b] += __shfl_xor_sync(0xffffffffu, s[b], 8);
                    s[b] += __shfl_xor_sync(0xffffffffu, s[b], 16);
                }
#pragma unroll
                for (int b = 0; b < 4; ++b) {
                    float h1v = tanhf(s[b]);
                    unsigned int la = smem_u32(&hbuf[OFF_H1F + ph1w * HPAR + b * HB + hpos]);
                    st_cluster(la, kc, h1v);
                    if (kc == 0) {
                        g_rnn[(long long)(b * TT + t) * DD + dg] = h1v;
                        if (t == TT - 1) g_final[BB * DD + b * DD + dg] = h1v;
                    }
                }
            }
            cluster_sync_all();
        }
    }
}

// ===========================================================================
// Kernel 3: head GEMM (unchanged, known good). 128x128 tiles, f32x2.
// ===========================================================================
#define BM 128
#define BV 128
#define BK 32
#define TP 132

__global__ __launch_bounds__(256) void head_kernel(
    const float* __restrict__ head_w,
    float* __restrict__ out)
{
    __shared__ __align__(16) float As[BK * TP];
    __shared__ __align__(16) float Bs[BK * TP];

    const int tid   = threadIdx.x;
    const int vTile = blockIdx.x;
    const int mTile = blockIdx.y;

    const int tv = tid & 15;
    const int tm = tid >> 4;
    const int lkq = tid & 7;
    const int lr0 = tid >> 3;

    u64 acc[8][4];
#pragma unroll
    for (int mi = 0; mi < 8; ++mi)
#pragma unroll
        for (int vp = 0; vp < 4; ++vp) acc[mi][vp] = 0ULL;

    const long long mBase = (long long)mTile * BM;
    const long long vBase = (long long)vTile * BV;

    for (int kc = 0; kc < DD; kc += BK) {
#pragma unroll
        for (int i = 0; i < 4; ++i) {
            int m = lr0 + 32 * i;
            float4 av = *(const float4*)(g_rnn + (mBase + m) * DD + kc + lkq * 4);
            As[(lkq * 4 + 0) * TP + m] = av.x;
            As[(lkq * 4 + 1) * TP + m] = av.y;
            As[(lkq * 4 + 2) * TP + m] = av.z;
            As[(lkq * 4 + 3) * TP + m] = av.w;

            int v = lr0 + 32 * i;
            float4 bv = *(const float4*)(head_w + (vBase + v) * DD + kc + lkq * 4);
            Bs[(lkq * 4 + 0) * TP + v] = bv.x;
            Bs[(lkq * 4 + 1) * TP + v] = bv.y;
            Bs[(lkq * 4 + 2) * TP + v] = bv.z;
            Bs[(lkq * 4 + 3) * TP + v] = bv.w;
        }
        __syncthreads();

#pragma unroll 8
        for (int k = 0; k < BK; ++k) {
            const float4* ap = (const float4*)(As + k * TP + tm * 8);
            float4 a0 = ap[0], a1 = ap[1];
            const ulonglong2* bp = (const ulonglong2*)(Bs + k * TP + tv * 8);
            ulonglong2 bq0 = bp[0], bq1 = bp[1];
            u64 bv0 = bq0.x, bv1 = bq0.y, bv2 = bq1.x, bv3 = bq1.y;
            float am[8] = {a0.x, a0.y, a0.z, a0.w, a1.x, a1.y, a1.z, a1.w};
#pragma unroll
            for (int mi = 0; mi < 8; ++mi) {
                u64 ad = dup2(am[mi]);
                acc[mi][0] = ffma2(ad, bv0, acc[mi][0]);
                acc[mi][1] = ffma2(ad, bv1, acc[mi][1]);
                acc[mi][2] = ffma2(ad, bv2, acc[mi][2]);
                acc[mi][3] = ffma2(ad, bv3, acc[mi][3]);
            }
        }
        __syncthreads();
    }

    const long long vOut = vBase + tv * 8;
#pragma unroll
    for (int mi = 0; mi < 8; ++mi) {
        long long row = mBase + tm * 8 + mi;
        float2 p0 = up2(acc[mi][0]);
        float2 p1 = up2(acc[mi][1]);
        float2 p2 = up2(acc[mi][2]);
        float2 p3 = up2(acc[mi][3]);
        float4 o0 = make_float4(p0.x, p0.y, p1.x, p1.y);
        float4 o1 = make_float4(p2.x, p2.y, p3.x, p3.y);
        float* dst = out + row * VV + vOut;
        *(float4*)(dst + 0) = o0;
        *(float4*)(dst + 4) = o1;
    }
}

// ===========================================================================
// Kernel 4: append final_hidden after logits if the output has room.
// ===========================================================================
__global__ void tail_kernel(float* __restrict__ out, int n)
{
    int i = blockIdx.x * blockDim.x + threadIdx.x;
    if (i < n) out[LOGITS_N + i] = g_final[i];
}

// ===========================================================================
extern "C" void kernel_launch(void* const* d_in, const int* in_sizes, int n_in,
                              void* d_out, int out_size)
{
    const int*   ids    = (const int*)  d_in[0];
    const float* embed  = (const float*)d_in[1];
    const float* W0     = (const float*)d_in[2];
    const float* b0     = (const float*)d_in[3];
    const float* W1     = (const float*)d_in[4];
    const float* b1     = (const float*)d_in[5];
    const float* head_w = (const float*)d_in[6];
    float* out = (float*)d_out;

    xproj_kernel<<<NROWS / 8, 256>>>(ids, embed, W0, b0);
    rnn_kernel<<<8, 384>>>(W0, W1, b1);
    head_kernel<<<dim3(VV / BV, NROWS / BM), 256>>>(head_w, out);

    long long extra = (long long)out_size - LOGITS_N;
    if (extra > 0) {
        int n = (int)(extra < 2LL * BB * DD ? extra : 2LL * BB * DD);
        tail_kernel<<<(n + 255) / 256, 256>>>(out, n);
    }
}